// round 14
// baseline (speedup 1.0000x reference)
#include <cuda_runtime.h>

#define NW 10
#define DIM 1024
#define WARPS_PER_BLK 4
#define GRID_BLOCKS 592          // 148 SMs x 4 resident blocks = one full wave
#define TOT_WARPS (GRID_BLOCKS * WARPS_PER_BLK)   // 2368

typedef unsigned long long u64;

// ---- packed f32x2 primitives ----
__device__ __forceinline__ u64 pk(float x, float y) {
    u64 r; asm("mov.b64 %0,{%1,%2};" : "=l"(r) : "f"(x), "f"(y)); return r;
}
__device__ __forceinline__ u64 pkb(float x) { return pk(x, x); }
__device__ __forceinline__ void upk(u64 a, float& x, float& y) {
    asm("mov.b64 {%0,%1},%2;" : "=f"(x), "=f"(y) : "l"(a));
}
__device__ __forceinline__ float hadd(u64 a) {
    float x, y; upk(a, x, y); return x + y;
}
__device__ __forceinline__ u64 f2fma(u64 a, u64 b, u64 c) {
    u64 d; asm("fma.rn.f32x2 %0,%1,%2,%3;" : "=l"(d) : "l"(a), "l"(b), "l"(c)); return d;
}
__device__ __forceinline__ u64 f2mul(u64 a, u64 b) {
    u64 d; asm("mul.rn.f32x2 %0,%1,%2;" : "=l"(d) : "l"(a), "l"(b)); return d;
}
__device__ __forceinline__ u64 f2add(u64 a, u64 b) {
    u64 d; asm("add.rn.f32x2 %0,%1,%2;" : "=l"(d) : "l"(a), "l"(b)); return d;
}
__device__ __forceinline__ u64 f2sub(u64 a, u64 b) {
    u64 d; asm("sub.rn.f32x2 %0,%1,%2;" : "=l"(d) : "l"(a), "l"(b)); return d;
}
__device__ __forceinline__ u64 swp(u64 a) {      // (x,y)->(y,x)
    float x, y; upk(a, x, y); return pk(y, x);
}
__device__ __forceinline__ u64 ldsv(const u64* p) {   // no cross-gate hoisting
    return *(const volatile u64*)p;
}

// XOR swizzle for conflict-free 32x32 8-byte transpose through shared memory.
__device__ __forceinline__ int swz(int idx) {
    return (idx & 0x3E0) | (((idx >> 5) ^ idx) & 31);
}

// Real RY butterfly on register bit K (packed complex amplitudes).
template<int K>
__device__ __forceinline__ void ryg(u64* a, const u64* cf) {
    const u64 cc = ldsv(cf + 0), ss = ldsv(cf + 1), nss = ldsv(cf + 2);
#pragma unroll
    for (int p = 0; p < 16; ++p) {
        const int m0 = ((p >> K) << (K + 1)) | (p & ((1 << K) - 1));
        const int m1 = m0 | (1 << K);
        u64 n0 = f2fma(cc, a[m0], f2mul(nss, a[m1]));
        u64 n1 = f2fma(ss, a[m0], f2mul(cc,  a[m1]));
        a[m0] = n0; a[m1] = n1;
    }
}

// ============================================================================
// Layer 1 ZYZ-factored: layer1 = Dphi * (prod_q RY_q) * Dlam (Dlam at load,
// Dphi applied in LB). Layer-2 RY + CNOT folded into observables (R7).
// Persistent single-wave grid: each warp handles 1-2 states; prep once per
// block, overlapped with the first state's global loads.
// ============================================================================

__global__ __launch_bounds__(128, 4)
void qsa13_kernel(const float* __restrict__ x,
                  const float* __restrict__ rx0,
                  const float* __restrict__ ry0,
                  const float* __restrict__ ry1,
                  float* __restrict__ out,
                  int n_states)
{
    __shared__ u64 buf[WARPS_PER_BLK][DIM];   // 8 KB per warp
    __shared__ u64 cry[NW][3];
    __shared__ u64 lamR[32], lamT[32], phiT[32], phiRc[32], phiRs[32];
    __shared__ float sphi[NW], slam[NW];
    __shared__ float cz[NW], cxw[NW];

    const int tid = threadIdx.x;
    const int w = tid >> 5;
    const int t = tid & 31;
    u64* sb = buf[w];

    // Stride assignment spreads doubled warps evenly across blocks/SMs.
    int s = blockIdx.x + GRID_BLOCKS * w;     // first state for this warp

    // ---- Issue state-1 loads FIRST (LA: i=(r<<5)|t); prep overlaps latency ----
    u64 a[32];
    {
        const float* xr = x + (size_t)s * DIM;
#pragma unroll
        for (int r = 0; r < 32; ++r) a[r] = pkb(xr[(r << 5) + t]);
    }

    // ---- Prep stage 1 (10 threads): ZYZ decomposition ----
    if (tid < NW) {
        float sx, cx_, s0, c0, s1, c1;
        sincosf(0.5f * rx0[tid], &sx, &cx_);
        sincosf(0.5f * ry0[tid], &s0, &c0);
        sincosf(0.5f * ry1[tid], &s1, &c1);
        // M = RY(ry0)*RX(rx0) = [[a, b], [-conj(b), conj(a)]]
        const float ar =  c0 * cx_;
        const float ai =  s0 * sx;
        const float br = -s0 * cx_;
        const float bi = -c0 * sx;
        // ZYZ: M = RZ(phi) RY(2T) RZ(lam)  (conventions validated R10-R12)
        const float uu = atan2f(ai, ar);
        const float vv = atan2f(-bi, -br);
        sphi[tid] = -(uu + vv);
        slam[tid] = vv - uu;
        const float cT = sqrtf(ar * ar + ai * ai);
        const float sT = sqrtf(br * br + bi * bi);
        cry[tid][0] = pkb(cT);
        cry[tid][1] = pkb(sT);
        cry[tid][2] = pkb(-sT);
        cz[tid]  = c1 * c1 - s1 * s1;
        cxw[tid] = -4.f * c1 * s1;       // half-sum X accumulation
    }
    __syncthreads();

    // ---- Prep stage 2: one table per warp, one sincosf per lane ----
    {
        float ang = 0.f;
        if (w == 0 || w == 2) {          // wires 0-4 pattern over 5-bit index t
            const float* src = (w == 0) ? slam : sphi;
#pragma unroll
            for (int k = 0; k < 5; ++k) if ((t >> (4 - k)) & 1) ang += src[k];
        } else {                          // wires 5-9 pattern
            const float* src = (w == 1) ? slam : sphi;
#pragma unroll
            for (int k = 5; k < 10; ++k) if ((t >> (9 - k)) & 1) ang += src[k];
        }
        float sa, ca;
        sincosf(ang, &sa, &ca);
        if      (w == 0) lamR[t] = pk(ca, sa);
        else if (w == 1) lamT[t] = pk(ca, sa);
        else if (w == 2) phiT[t] = pk(ca, sa);
        else { phiRc[t] = pkb(ca); phiRs[t] = pk(-sa, sa); }
    }
    __syncthreads();

    // ================= Per-state loop (1 or 2 iterations) ==================
    bool preloaded = true;
    for (;;) {
        if (!preloaded) {
            const float* xr = x + (size_t)s * DIM;
#pragma unroll
            for (int r = 0; r < 32; ++r) a[r] = pkb(xr[(r << 5) + t]);
        }

        // ---- Sum of squares ----
        u64 sq = 0ull;
#pragma unroll
        for (int r = 0; r < 32; ++r) sq = f2fma(a[r], a[r], sq);
        float sumsq, dmy;
        upk(sq, sumsq, dmy);
#pragma unroll
        for (int off = 16; off; off >>= 1)
            sumsq += __shfl_xor_sync(0xffffffffu, sumsq, off);
        const float inv = 1.f / fmaxf(sqrtf(sumsq), 1e-12f);

        // ---- Init: a[i] = v * inv * e^{i lam(i)} (input real -> plain mul) ----
        {
            float ct, st;
            upk(lamT[t], ct, st);
            const u64 T1 = pkb(ct * inv);
            const u64 T2 = pk(-st * inv, st * inv);
#pragma unroll
            for (int r = 0; r < 32; ++r) {
                u64 z = ldsv(lamR + r);
                a[r] = f2mul(a[r], f2fma(z, T1, f2mul(swp(z), T2)));
            }
        }

        // ---- Phase A: RY on wires 0..4 (wire q -> reg bit K=4-q) ----
        ryg<4>(a, cry[0]);
        ryg<3>(a, cry[1]);
        ryg<2>(a, cry[2]);
        ryg<1>(a, cry[3]);
        ryg<0>(a, cry[4]);

        // ---- Remap LA -> LB (transpose) ----
        __syncwarp();
#pragma unroll
        for (int r = 0; r < 32; ++r) sb[swz((r << 5) | t)] = a[r];
        __syncwarp();
#pragma unroll
        for (int r = 0; r < 32; ++r) a[r] = sb[swz((t << 5) | r)];

        // ---- Phase B: RY on wires 5..9 (wire q -> reg bit K=9-q) ----
        ryg<4>(a, cry[5]);
        ryg<3>(a, cry[6]);
        ryg<2>(a, cry[7]);
        ryg<1>(a, cry[8]);
        ryg<0>(a, cry[9]);

        // ---- Apply Dphi (separable in LB: t-part wires 0-4, r-part 5-9) ----
        {
            float cpt, spt;
            upk(phiT[t], cpt, spt);
            const u64 T1b = pkb(cpt);
            const u64 T2b = pk(-spt, spt);
#pragma unroll
            for (int r = 0; r < 32; ++r) {
                u64 v = f2fma(a[r], ldsv(phiRc + r), f2mul(swp(a[r]), ldsv(phiRs + r)));
                a[r] = f2fma(v, T1b, f2mul(swp(v), T2b));
            }
        }

        // ================== Epilogue on psi (LB: j=(t<<5)|r) ================

        // Z-part: tot + 5 signed r-sums via quad butterflies.
        u64 tot = 0, S10 = 0, S18 = 0, S1C = 0, S1E = 0, S1F = 0;
#pragma unroll
        for (int r = 0; r < 32; r += 4) {
            u64 q0 = f2mul(a[r],     a[r]);
            u64 q1 = f2mul(a[r + 1], a[r + 1]);
            u64 q2 = f2mul(a[r + 2], a[r + 2]);
            u64 q3 = f2mul(a[r + 3], a[r + 3]);
            u64 s01 = f2add(q0, q1), s23 = f2add(q2, q3);
            u64 d01 = f2sub(q0, q1), d23 = f2sub(q2, q3);
            u64 ss = f2add(s01, s23);
            u64 sd = f2sub(s01, s23);
            u64 df = f2sub(d01, d23);
            const int pq = ((r >> 4) ^ (r >> 3) ^ (r >> 2)) & 1;
            tot = f2add(tot, ss);
            S10 = (r & 0x10)                  ? f2sub(S10, ss) : f2add(S10, ss);
            S18 = (((r >> 4) ^ (r >> 3)) & 1) ? f2sub(S18, ss) : f2add(S18, ss);
            S1C = pq ? f2sub(S1C, ss) : f2add(S1C, ss);
            S1E = pq ? f2sub(S1E, sd) : f2add(S1E, sd);
            S1F = pq ? f2sub(S1F, df) : f2add(S1F, df);
        }
        const float tot_s = hadd(tot);
        const float s10 = hadd(S10), s18 = hadd(S18), s1C = hadd(S1C);
        const float s1E = hadd(S1E), s1F = hadd(S1F);

        // X in-register wires 5..8 (partners r^0x18, r^0xC, r^6, r^3), half-sums.
        u64 X5 = 0, X6 = 0, X7 = 0, X8 = 0;
#pragma unroll
        for (int r = 0; r < 32; ++r) {
            if (!(r & 0x10)) X5 = f2fma(a[r], a[r ^ 0x18], X5);
            if (!(r & 0x08)) X6 = f2fma(a[r], a[r ^ 0x0C], X6);
            if (!(r & 0x04)) X7 = f2fma(a[r], a[r ^ 0x06], X7);
            if (!(r & 0x02)) X8 = f2fma(a[r], a[r ^ 0x03], X8);
        }
        const float x5 = hadd(X5), x6 = hadd(X6), x7 = hadd(X7), x8 = hadd(X8);

        // Straddler X wires, half-sums:
        //  w4 (m=0x30): pairs (t, r<16) <-> (t^1, r+16)
        //  w9 (m=0x301): pairs (t, r even) <-> (t^0x18, r+1)
        u64 X4 = 0, X9 = 0;
#pragma unroll
        for (int r = 0; r < 16; ++r) {
            u64 p4 = __shfl_xor_sync(0xffffffffu, a[r + 16], 1);
            X4 = f2fma(a[r], p4, X4);
        }
#pragma unroll
        for (int r = 0; r < 32; r += 2) {
            u64 p9 = __shfl_xor_sync(0xffffffffu, a[r + 1], 0x18);
            X9 = f2fma(a[r], p9, X9);
        }
        const float x4 = hadd(X4), x9 = hadd(X9);

        // ---- Transpose LB -> LA for wires 0..3 X-terms ----
        __syncwarp();
#pragma unroll
        for (int r = 0; r < 32; ++r) sb[swz((t << 5) | r)] = a[r];
        __syncwarp();
#pragma unroll
        for (int r = 0; r < 32; ++r) a[r] = sb[swz((r << 5) | t)];

        // X in-register wires 0..3 in LA (partners r^0x18, r^0xC, r^6, r^3).
        u64 X0 = 0, X1 = 0, X2 = 0, X3 = 0;
#pragma unroll
        for (int r = 0; r < 32; ++r) {
            if (!(r & 0x10)) X0 = f2fma(a[r], a[r ^ 0x18], X0);
            if (!(r & 0x08)) X1 = f2fma(a[r], a[r ^ 0x0C], X1);
            if (!(r & 0x04)) X2 = f2fma(a[r], a[r ^ 0x06], X2);
            if (!(r & 0x02)) X3 = f2fma(a[r], a[r ^ 0x03], X3);
        }
        const float x0 = hadd(X0), x1 = hadd(X1), x2 = hadd(X2), x3 = hadd(X3);

        // Thread-parity signs for the Z parts (t-masks from M_b >> 5).
        const float sgA = (__popc(t & 0x0F) & 1) ? -1.f : 1.f;   // wire 0
        const float sgB = (__popc(t & 0x18) & 1) ? -1.f : 1.f;   // wire 1
        const float sgC = (__popc(t & 0x1C) & 1) ? -1.f : 1.f;   // wire 2
        const float sgD = (__popc(t & 0x1E) & 1) ? -1.f : 1.f;   // wire 3
        const float sgE = (__popc(t & 0x1F) & 1) ? -1.f : 1.f;   // wires 4..9

        // Combine: E_q = cz[q] * Z_q + cxw[q] * X_q  (per-thread partials).
        float e[NW];
        e[0] = cz[0] * (sgA * s1F)   + cxw[0] * x0;
        e[1] = cz[1] * (sgB * tot_s) + cxw[1] * x1;
        e[2] = cz[2] * (sgC * tot_s) + cxw[2] * x2;
        e[3] = cz[3] * (sgD * tot_s) + cxw[3] * x3;
        e[4] = cz[4] * (sgE * tot_s) + cxw[4] * x4;
        e[5] = cz[5] * (sgE * s10)   + cxw[5] * x5;
        e[6] = cz[6] * (sgE * s18)   + cxw[6] * x6;
        e[7] = cz[7] * (sgE * s1C)   + cxw[7] * x7;
        e[8] = cz[8] * (sgE * s1E)   + cxw[8] * x8;
        e[9] = cz[9] * (sgE * s1F)   + cxw[9] * x9;

        // Packed warp reduction of 10 values as 5 u64.
        u64 vp[5];
#pragma unroll
        for (int j = 0; j < 5; ++j) vp[j] = pk(e[2 * j], e[2 * j + 1]);
#pragma unroll
        for (int off = 16; off; off >>= 1) {
#pragma unroll
            for (int j = 0; j < 5; ++j)
                vp[j] = f2add(vp[j], __shfl_xor_sync(0xffffffffu, vp[j], off));
        }
        if (t == 0) {
#pragma unroll
            for (int j = 0; j < 5; ++j) {
                float vx, vy;
                upk(vp[j], vx, vy);
                out[(size_t)s * NW + 2 * j]     = vx;
                out[(size_t)s * NW + 2 * j + 1] = vy;
            }
        }

        // ---- Next state for this warp? ----
        if (s + TOT_WARPS < n_states) { s += TOT_WARPS; preloaded = false; }
        else break;
    }
}

extern "C" void kernel_launch(void* const* d_in, const int* in_sizes, int n_in,
                              void* d_out, int out_size) {
    const float* x   = (const float*)d_in[0];
    const float* rx0 = (const float*)d_in[1];
    const float* ry0 = (const float*)d_in[2];
    const float* ry1 = (const float*)d_in[3];
    float* out = (float*)d_out;
    const int n_states = in_sizes[0] / DIM;            // 4096
    qsa13_kernel<<<GRID_BLOCKS, 32 * WARPS_PER_BLK>>>(x, rx0, ry0, ry1, out, n_states);
}

// round 15
// speedup vs baseline: 1.1411x; 1.1411x over previous
#include <cuda_runtime.h>

#define NW 10
#define DIM 1024
#define WARPS_PER_BLK 4

typedef unsigned long long u64;

// ---- packed f32x2 primitives ----
__device__ __forceinline__ u64 pk(float x, float y) {
    u64 r; asm("mov.b64 %0,{%1,%2};" : "=l"(r) : "f"(x), "f"(y)); return r;
}
__device__ __forceinline__ u64 pkb(float x) { return pk(x, x); }
__device__ __forceinline__ void upk(u64 a, float& x, float& y) {
    asm("mov.b64 {%0,%1},%2;" : "=f"(x), "=f"(y) : "l"(a));
}
__device__ __forceinline__ float hadd(u64 a) {
    float x, y; upk(a, x, y); return x + y;
}
__device__ __forceinline__ u64 f2fma(u64 a, u64 b, u64 c) {
    u64 d; asm("fma.rn.f32x2 %0,%1,%2,%3;" : "=l"(d) : "l"(a), "l"(b), "l"(c)); return d;
}
__device__ __forceinline__ u64 f2mul(u64 a, u64 b) {
    u64 d; asm("mul.rn.f32x2 %0,%1,%2;" : "=l"(d) : "l"(a), "l"(b)); return d;
}
__device__ __forceinline__ u64 f2add(u64 a, u64 b) {
    u64 d; asm("add.rn.f32x2 %0,%1,%2;" : "=l"(d) : "l"(a), "l"(b)); return d;
}
__device__ __forceinline__ u64 f2sub(u64 a, u64 b) {
    u64 d; asm("sub.rn.f32x2 %0,%1,%2;" : "=l"(d) : "l"(a), "l"(b)); return d;
}
__device__ __forceinline__ u64 swp(u64 a) {      // (x,y)->(y,x)
    float x, y; upk(a, x, y); return pk(y, x);
}
__device__ __forceinline__ u64 ldsv(const u64* p) {   // no cross-gate hoisting
    return *(const volatile u64*)p;
}

// XOR swizzle for conflict-free 32x32 8-byte transpose through shared memory.
__device__ __forceinline__ int swz(int idx) {
    return (idx & 0x3E0) | (((idx >> 5) ^ idx) & 31);
}

// Real RY butterfly on register bit K (packed complex amplitudes).
template<int K>
__device__ __forceinline__ void ryg(u64* a, const u64* cf) {
    const u64 cc = ldsv(cf + 0), ss = ldsv(cf + 1), nss = ldsv(cf + 2);
#pragma unroll
    for (int p = 0; p < 16; ++p) {
        const int m0 = ((p >> K) << (K + 1)) | (p & ((1 << K) - 1));
        const int m1 = m0 | (1 << K);
        u64 n0 = f2fma(cc, a[m0], f2mul(nss, a[m1]));
        u64 n1 = f2fma(ss, a[m0], f2mul(cc,  a[m1]));
        a[m0] = n0; a[m1] = n1;
    }
}

// ============================================================================
// Layer 1 ZYZ-factored: layer1 = Dphi * (prod_q RY_q) * Dlam.
//  - Dlam applied at load (input real).
//  - Dphi_t (wires 0-4; t-indexed in LB) commutes with phase-B gates ->
//    folded into the transpose LOAD (overlaps LDS latency).
//  - Dphi_r (wires 5-9) applied after phase B.
// Layer-2 RY + CNOT folded into observables (R7 derivation).
// Per-block prep overlapped with the state LDGs (issued first).
// ============================================================================

__global__ __launch_bounds__(128, 4)
void qsa14_kernel(const float* __restrict__ x,
                  const float* __restrict__ rx0,
                  const float* __restrict__ ry0,
                  const float* __restrict__ ry1,
                  float* __restrict__ out)
{
    __shared__ u64 buf[WARPS_PER_BLK][DIM];   // 8 KB per warp
    __shared__ u64 cry[NW][3];
    __shared__ u64 lamR[32], lamT[32], phiT[32], phiRc[32], phiRs[32];
    __shared__ float sphi[NW], slam[NW];
    __shared__ float cz[NW], cxw[NW];

    const int tid = threadIdx.x;
    const int w = tid >> 5;
    const int t = tid & 31;
    const int n = blockIdx.x * WARPS_PER_BLK + w;   // state 0..4095
    u64* sb = buf[w];

    // ---- Issue state loads FIRST (LA: i=(r<<5)|t); prep overlaps the latency ----
    u64 a[32];
    const float* xr = x + (size_t)n * DIM;
#pragma unroll
    for (int r = 0; r < 32; ++r) a[r] = pkb(xr[(r << 5) + t]);

    // ---- Prep stage 1 (10 threads): ZYZ decomposition ----
    if (tid < NW) {
        float sx, cx_, s0, c0, s1, c1;
        sincosf(0.5f * rx0[tid], &sx, &cx_);
        sincosf(0.5f * ry0[tid], &s0, &c0);
        sincosf(0.5f * ry1[tid], &s1, &c1);
        // M = RY(ry0)*RX(rx0) = [[a, b], [-conj(b), conj(a)]]
        const float ar =  c0 * cx_;
        const float ai =  s0 * sx;
        const float br = -s0 * cx_;
        const float bi = -c0 * sx;
        // ZYZ: M = RZ(phi) RY(2T) RZ(lam)  (conventions validated R10-R12)
        const float uu = atan2f(ai, ar);
        const float vv = atan2f(-bi, -br);
        sphi[tid] = -(uu + vv);
        slam[tid] = vv - uu;
        const float cT = sqrtf(ar * ar + ai * ai);
        const float sT = sqrtf(br * br + bi * bi);
        cry[tid][0] = pkb(cT);
        cry[tid][1] = pkb(sT);
        cry[tid][2] = pkb(-sT);
        cz[tid]  = c1 * c1 - s1 * s1;
        cxw[tid] = -4.f * c1 * s1;       // half-sum X accumulation
    }
    __syncthreads();

    // ---- Prep stage 2: one table per warp, one sincosf per lane ----
    {
        float ang = 0.f;
        if (w == 0 || w == 2) {          // wires 0-4 pattern over 5-bit index t
            const float* src = (w == 0) ? slam : sphi;
#pragma unroll
            for (int k = 0; k < 5; ++k) if ((t >> (4 - k)) & 1) ang += src[k];
        } else {                          // wires 5-9 pattern
            const float* src = (w == 1) ? slam : sphi;
#pragma unroll
            for (int k = 5; k < 10; ++k) if ((t >> (9 - k)) & 1) ang += src[k];
        }
        float sa, ca;
        sincosf(ang, &sa, &ca);
        if      (w == 0) lamR[t] = pk(ca, sa);
        else if (w == 1) lamT[t] = pk(ca, sa);
        else if (w == 2) phiT[t] = pk(ca, sa);
        else { phiRc[t] = pkb(ca); phiRs[t] = pk(-sa, sa); }
    }
    __syncthreads();

    // ---- Sum of squares (loads have landed) ----
    u64 sq = 0ull;
#pragma unroll
    for (int r = 0; r < 32; ++r) sq = f2fma(a[r], a[r], sq);
    float sumsq, dmy;
    upk(sq, sumsq, dmy);
#pragma unroll
    for (int off = 16; off; off >>= 1)
        sumsq += __shfl_xor_sync(0xffffffffu, sumsq, off);
    const float inv = 1.f / fmaxf(sqrtf(sumsq), 1e-12f);

    // ---- Init: a[i] = v * inv * e^{i lam(i)}  (input real -> plain mul) ----
    {
        float ct, st;
        upk(lamT[t], ct, st);
        const u64 T1 = pkb(ct * inv);
        const u64 T2 = pk(-st * inv, st * inv);
#pragma unroll
        for (int r = 0; r < 32; ++r) {
            u64 z = ldsv(lamR + r);
            a[r] = f2mul(a[r], f2fma(z, T1, f2mul(swp(z), T2)));
        }
    }

    // ---- Phase A: RY on wires 0..4 (wire q -> reg bit K=4-q) ----
    ryg<4>(a, cry[0]);
    ryg<3>(a, cry[1]);
    ryg<2>(a, cry[2]);
    ryg<1>(a, cry[3]);
    ryg<0>(a, cry[4]);

    // ---- Remap LA -> LB (transpose) with Dphi_t folded into the load ----
    // Dphi_t acts on wires 0-4 = t-bits in LB; it commutes with phase-B gates.
    __syncwarp();
#pragma unroll
    for (int r = 0; r < 32; ++r) sb[swz((r << 5) | t)] = a[r];
    __syncwarp();
    {
        float cpt, spt;
        upk(phiT[t], cpt, spt);
        const u64 T1b = pkb(cpt);
        const u64 T2b = pk(-spt, spt);
#pragma unroll
        for (int r = 0; r < 32; ++r) {
            u64 v = sb[swz((t << 5) | r)];
            a[r] = f2fma(v, T1b, f2mul(swp(v), T2b));
        }
    }

    // ---- Phase B: RY on wires 5..9 (wire q -> reg bit K=9-q) ----
    ryg<4>(a, cry[5]);
    ryg<3>(a, cry[6]);
    ryg<2>(a, cry[7]);
    ryg<1>(a, cry[8]);
    ryg<0>(a, cry[9]);

    // ---- Apply remaining Dphi_r (wires 5-9; r-indexed in LB) ----
#pragma unroll
    for (int r = 0; r < 32; ++r)
        a[r] = f2fma(a[r], ldsv(phiRc + r), f2mul(swp(a[r]), ldsv(phiRs + r)));

    // ======================= Epilogue on psi (LB: j=(t<<5)|r) ================
    // (identical to the validated R9/R11/R12 epilogue)

    // Z-part: tot + 5 signed r-sums via quad butterflies.
    u64 tot = 0, S10 = 0, S18 = 0, S1C = 0, S1E = 0, S1F = 0;
#pragma unroll
    for (int r = 0; r < 32; r += 4) {
        u64 q0 = f2mul(a[r],     a[r]);
        u64 q1 = f2mul(a[r + 1], a[r + 1]);
        u64 q2 = f2mul(a[r + 2], a[r + 2]);
        u64 q3 = f2mul(a[r + 3], a[r + 3]);
        u64 s01 = f2add(q0, q1), s23 = f2add(q2, q3);
        u64 d01 = f2sub(q0, q1), d23 = f2sub(q2, q3);
        u64 ss = f2add(s01, s23);
        u64 sd = f2sub(s01, s23);
        u64 df = f2sub(d01, d23);
        const int pq = ((r >> 4) ^ (r >> 3) ^ (r >> 2)) & 1;
        tot = f2add(tot, ss);
        S10 = (r & 0x10)                  ? f2sub(S10, ss) : f2add(S10, ss);
        S18 = (((r >> 4) ^ (r >> 3)) & 1) ? f2sub(S18, ss) : f2add(S18, ss);
        S1C = pq ? f2sub(S1C, ss) : f2add(S1C, ss);
        S1E = pq ? f2sub(S1E, sd) : f2add(S1E, sd);
        S1F = pq ? f2sub(S1F, df) : f2add(S1F, df);
    }
    const float tot_s = hadd(tot);
    const float s10 = hadd(S10), s18 = hadd(S18), s1C = hadd(S1C);
    const float s1E = hadd(S1E), s1F = hadd(S1F);

    // X in-register wires 5..8 (partners r^0x18, r^0xC, r^6, r^3), half-sums.
    u64 X5 = 0, X6 = 0, X7 = 0, X8 = 0;
#pragma unroll
    for (int r = 0; r < 32; ++r) {
        if (!(r & 0x10)) X5 = f2fma(a[r], a[r ^ 0x18], X5);
        if (!(r & 0x08)) X6 = f2fma(a[r], a[r ^ 0x0C], X6);
        if (!(r & 0x04)) X7 = f2fma(a[r], a[r ^ 0x06], X7);
        if (!(r & 0x02)) X8 = f2fma(a[r], a[r ^ 0x03], X8);
    }
    const float x5 = hadd(X5), x6 = hadd(X6), x7 = hadd(X7), x8 = hadd(X8);

    // Straddler X wires, half-sums:
    //  w4 (m=0x30): pairs (t, r<16) <-> (t^1, r+16)
    //  w9 (m=0x301): pairs (t, r even) <-> (t^0x18, r+1)
    u64 X4 = 0, X9 = 0;
#pragma unroll
    for (int r = 0; r < 16; ++r) {
        u64 p4 = __shfl_xor_sync(0xffffffffu, a[r + 16], 1);
        X4 = f2fma(a[r], p4, X4);
    }
#pragma unroll
    for (int r = 0; r < 32; r += 2) {
        u64 p9 = __shfl_xor_sync(0xffffffffu, a[r + 1], 0x18);
        X9 = f2fma(a[r], p9, X9);
    }
    const float x4 = hadd(X4), x9 = hadd(X9);

    // ---- Transpose LB -> LA for wires 0..3 X-terms ----
    __syncwarp();
#pragma unroll
    for (int r = 0; r < 32; ++r) sb[swz((t << 5) | r)] = a[r];
    __syncwarp();
#pragma unroll
    for (int r = 0; r < 32; ++r) a[r] = sb[swz((r << 5) | t)];

    // X in-register wires 0..3 in LA (partners r^0x18, r^0xC, r^6, r^3), half-sums.
    u64 X0 = 0, X1 = 0, X2 = 0, X3 = 0;
#pragma unroll
    for (int r = 0; r < 32; ++r) {
        if (!(r & 0x10)) X0 = f2fma(a[r], a[r ^ 0x18], X0);
        if (!(r & 0x08)) X1 = f2fma(a[r], a[r ^ 0x0C], X1);
        if (!(r & 0x04)) X2 = f2fma(a[r], a[r ^ 0x06], X2);
        if (!(r & 0x02)) X3 = f2fma(a[r], a[r ^ 0x03], X3);
    }
    const float x0 = hadd(X0), x1 = hadd(X1), x2 = hadd(X2), x3 = hadd(X3);

    // Thread-parity signs for the Z parts (t-masks from M_b >> 5).
    const float sgA = (__popc(t & 0x0F) & 1) ? -1.f : 1.f;   // wire 0
    const float sgB = (__popc(t & 0x18) & 1) ? -1.f : 1.f;   // wire 1
    const float sgC = (__popc(t & 0x1C) & 1) ? -1.f : 1.f;   // wire 2
    const float sgD = (__popc(t & 0x1E) & 1) ? -1.f : 1.f;   // wire 3
    const float sgE = (__popc(t & 0x1F) & 1) ? -1.f : 1.f;   // wires 4..9

    // Combine: E_q = cz[q] * Z_q + cxw[q] * X_q  (per-thread partials).
    float e[NW];
    e[0] = cz[0] * (sgA * s1F)   + cxw[0] * x0;
    e[1] = cz[1] * (sgB * tot_s) + cxw[1] * x1;
    e[2] = cz[2] * (sgC * tot_s) + cxw[2] * x2;
    e[3] = cz[3] * (sgD * tot_s) + cxw[3] * x3;
    e[4] = cz[4] * (sgE * tot_s) + cxw[4] * x4;
    e[5] = cz[5] * (sgE * s10)   + cxw[5] * x5;
    e[6] = cz[6] * (sgE * s18)   + cxw[6] * x6;
    e[7] = cz[7] * (sgE * s1C)   + cxw[7] * x7;
    e[8] = cz[8] * (sgE * s1E)   + cxw[8] * x8;
    e[9] = cz[9] * (sgE * s1F)   + cxw[9] * x9;

    // Packed warp reduction of 10 values as 5 u64.
    u64 vp[5];
#pragma unroll
    for (int j = 0; j < 5; ++j) vp[j] = pk(e[2 * j], e[2 * j + 1]);
#pragma unroll
    for (int off = 16; off; off >>= 1) {
#pragma unroll
        for (int j = 0; j < 5; ++j)
            vp[j] = f2add(vp[j], __shfl_xor_sync(0xffffffffu, vp[j], off));
    }
    if (t == 0) {
#pragma unroll
        for (int j = 0; j < 5; ++j) {
            float vx, vy;
            upk(vp[j], vx, vy);
            out[(size_t)n * NW + 2 * j]     = vx;
            out[(size_t)n * NW + 2 * j + 1] = vy;
        }
    }
}

extern "C" void kernel_launch(void* const* d_in, const int* in_sizes, int n_in,
                              void* d_out, int out_size) {
    const float* x   = (const float*)d_in[0];
    const float* rx0 = (const float*)d_in[1];
    const float* ry0 = (const float*)d_in[2];
    const float* ry1 = (const float*)d_in[3];
    float* out = (float*)d_out;
    const int n_states = in_sizes[0] / DIM;            // 4096
    qsa14_kernel<<<n_states / WARPS_PER_BLK, 32 * WARPS_PER_BLK>>>(x, rx0, ry0, ry1, out);
}

// round 16
// speedup vs baseline: 1.2154x; 1.0651x over previous
#include <cuda_runtime.h>

#define NW 10
#define DIM 1024
#define WARPS_PER_BLK 4

typedef unsigned long long u64;

// ---- packed f32x2 primitives ----
__device__ __forceinline__ u64 pk(float x, float y) {
    u64 r; asm("mov.b64 %0,{%1,%2};" : "=l"(r) : "f"(x), "f"(y)); return r;
}
__device__ __forceinline__ u64 pkb(float x) { return pk(x, x); }
__device__ __forceinline__ void upk(u64 a, float& x, float& y) {
    asm("mov.b64 {%0,%1},%2;" : "=f"(x), "=f"(y) : "l"(a));
}
__device__ __forceinline__ float hadd(u64 a) {
    float x, y; upk(a, x, y); return x + y;
}
__device__ __forceinline__ u64 f2fma(u64 a, u64 b, u64 c) {
    u64 d; asm("fma.rn.f32x2 %0,%1,%2,%3;" : "=l"(d) : "l"(a), "l"(b), "l"(c)); return d;
}
__device__ __forceinline__ u64 f2mul(u64 a, u64 b) {
    u64 d; asm("mul.rn.f32x2 %0,%1,%2;" : "=l"(d) : "l"(a), "l"(b)); return d;
}
__device__ __forceinline__ u64 f2add(u64 a, u64 b) {
    u64 d; asm("add.rn.f32x2 %0,%1,%2;" : "=l"(d) : "l"(a), "l"(b)); return d;
}
__device__ __forceinline__ u64 f2sub(u64 a, u64 b) {
    u64 d; asm("sub.rn.f32x2 %0,%1,%2;" : "=l"(d) : "l"(a), "l"(b)); return d;
}
__device__ __forceinline__ u64 swp(u64 a) {      // (x,y)->(y,x)
    float x, y; upk(a, x, y); return pk(y, x);
}
__device__ __forceinline__ u64 ldsv(const u64* p) {   // no cross-gate hoisting
    return *(const volatile u64*)p;
}

// XOR swizzle for conflict-free 32x32 8-byte transpose through shared memory.
__device__ __forceinline__ int swz(int idx) {
    return (idx & 0x3E0) | (((idx >> 5) ^ idx) & 31);
}

// Tangent-form RY butterfly on register bit K:
//   gate = cosT * [[1, -t],[t, 1]],  cosT folded into the global prefactor.
//   n0 = a0 - t a1 ; n1 = t a0 + a1   -> ONE fma per output.
template<int K>
__device__ __forceinline__ void ryt(u64* a, const u64* cf) {
    const u64 tt = ldsv(cf + 0), nt = ldsv(cf + 1);
#pragma unroll
    for (int p = 0; p < 16; ++p) {
        const int m0 = ((p >> K) << (K + 1)) | (p & ((1 << K) - 1));
        const int m1 = m0 | (1 << K);
        u64 a0 = a[m0], a1 = a[m1];
        a[m0] = f2fma(nt, a1, a0);
        a[m1] = f2fma(tt, a0, a1);
    }
}

// ============================================================================
// Layer 1 ZYZ-factored: layer1 = Dphi * (prod_q RY_q) * Dlam.
//  - Dlam applied at load (input real); global prefactor P = prod cosT_q
//    folded into the same scale.
//  - RY gates in tangent (Givens) form: 2 fma per butterfly.
//  - Dphi_t folded into the transpose load; Dphi_r applied after phase B.
// Layer-2 RY + CNOT folded into observables (R7 derivation).
// Per-block prep overlapped with the state LDGs (issued first).
// ============================================================================

__global__ __launch_bounds__(128, 4)
void qsa15_kernel(const float* __restrict__ x,
                  const float* __restrict__ rx0,
                  const float* __restrict__ ry0,
                  const float* __restrict__ ry1,
                  float* __restrict__ out)
{
    __shared__ u64 buf[WARPS_PER_BLK][DIM];   // 8 KB per warp
    __shared__ u64 cry[NW][2];                // tangent coeffs (t, -t)
    __shared__ u64 lamR[32], lamT[32], phiT[32], phiRc[32], phiRs[32];
    __shared__ float sphi[NW], slam[NW], scT[NW];
    __shared__ float cz[NW], cxw[NW];
    __shared__ float sPf;                     // prod of cosT_q

    const int tid = threadIdx.x;
    const int w = tid >> 5;
    const int t = tid & 31;
    const int n = blockIdx.x * WARPS_PER_BLK + w;   // state 0..4095
    u64* sb = buf[w];

    // ---- Issue state loads FIRST (LA: i=(r<<5)|t); prep overlaps the latency ----
    u64 a[32];
    const float* xr = x + (size_t)n * DIM;
#pragma unroll
    for (int r = 0; r < 32; ++r) a[r] = pkb(xr[(r << 5) + t]);

    // ---- Prep stage 1 (10 threads): ZYZ decomposition ----
    if (tid < NW) {
        float sx, cx_, s0, c0, s1, c1;
        sincosf(0.5f * rx0[tid], &sx, &cx_);
        sincosf(0.5f * ry0[tid], &s0, &c0);
        sincosf(0.5f * ry1[tid], &s1, &c1);
        // M = RY(ry0)*RX(rx0) = [[a, b], [-conj(b), conj(a)]]
        const float ar =  c0 * cx_;
        const float ai =  s0 * sx;
        const float br = -s0 * cx_;
        const float bi = -c0 * sx;
        // ZYZ: M = RZ(phi) RY(2T) RZ(lam)  (conventions validated R10-R14)
        const float uu = atan2f(ai, ar);
        const float vv = atan2f(-bi, -br);
        sphi[tid] = -(uu + vv);
        slam[tid] = vv - uu;
        const float cT = sqrtf(ar * ar + ai * ai);
        const float sT = sqrtf(br * br + bi * bi);
        const float tg = sT / cT;            // tangent form; cT folded into prefactor
        scT[tid] = cT;
        cry[tid][0] = pkb(tg);
        cry[tid][1] = pkb(-tg);
        cz[tid]  = c1 * c1 - s1 * s1;
        cxw[tid] = -4.f * c1 * s1;           // half-sum X accumulation
    }
    __syncthreads();

    // ---- Prep stage 2: one table per warp, one sincosf per lane ----
    {
        float ang = 0.f;
        if (w == 0 || w == 2) {          // wires 0-4 pattern over 5-bit index t
            const float* src = (w == 0) ? slam : sphi;
#pragma unroll
            for (int k = 0; k < 5; ++k) if ((t >> (4 - k)) & 1) ang += src[k];
        } else {                          // wires 5-9 pattern
            const float* src = (w == 1) ? slam : sphi;
#pragma unroll
            for (int k = 5; k < 10; ++k) if ((t >> (9 - k)) & 1) ang += src[k];
        }
        float sa, ca;
        sincosf(ang, &sa, &ca);
        if      (w == 0) lamR[t] = pk(ca, sa);
        else if (w == 1) lamT[t] = pk(ca, sa);
        else if (w == 2) phiT[t] = pk(ca, sa);
        else { phiRc[t] = pkb(ca); phiRs[t] = pk(-sa, sa); }
    }
    if (tid == 0) {
        float P = scT[0];
#pragma unroll
        for (int k = 1; k < NW; ++k) P *= scT[k];
        sPf = P;
    }
    __syncthreads();

    // ---- Sum of squares (loads have landed) ----
    u64 sq = 0ull;
#pragma unroll
    for (int r = 0; r < 32; ++r) sq = f2fma(a[r], a[r], sq);
    float sumsq, dmy;
    upk(sq, sumsq, dmy);
#pragma unroll
    for (int off = 16; off; off >>= 1)
        sumsq += __shfl_xor_sync(0xffffffffu, sumsq, off);
    const float inv = sPf / fmaxf(sqrtf(sumsq), 1e-12f);   // norm * gate prefactor

    // ---- Init: a[i] = v * inv * e^{i lam(i)}  (input real -> plain mul) ----
    {
        float ct, st;
        upk(lamT[t], ct, st);
        const u64 T1 = pkb(ct * inv);
        const u64 T2 = pk(-st * inv, st * inv);
#pragma unroll
        for (int r = 0; r < 32; ++r) {
            u64 z = ldsv(lamR + r);
            a[r] = f2mul(a[r], f2fma(z, T1, f2mul(swp(z), T2)));
        }
    }

    // ---- Phase A: tangent RY on wires 0..4 (wire q -> reg bit K=4-q) ----
    ryt<4>(a, cry[0]);
    ryt<3>(a, cry[1]);
    ryt<2>(a, cry[2]);
    ryt<1>(a, cry[3]);
    ryt<0>(a, cry[4]);

    // ---- Remap LA -> LB (transpose) with Dphi_t folded into the load ----
    __syncwarp();
#pragma unroll
    for (int r = 0; r < 32; ++r) sb[swz((r << 5) | t)] = a[r];
    __syncwarp();
    {
        float cpt, spt;
        upk(phiT[t], cpt, spt);
        const u64 T1b = pkb(cpt);
        const u64 T2b = pk(-spt, spt);
#pragma unroll
        for (int r = 0; r < 32; ++r) {
            u64 v = sb[swz((t << 5) | r)];
            a[r] = f2fma(v, T1b, f2mul(swp(v), T2b));
        }
    }

    // ---- Phase B: tangent RY on wires 5..9 (wire q -> reg bit K=9-q) ----
    ryt<4>(a, cry[5]);
    ryt<3>(a, cry[6]);
    ryt<2>(a, cry[7]);
    ryt<1>(a, cry[8]);
    ryt<0>(a, cry[9]);

    // ---- Apply remaining Dphi_r (wires 5-9; r-indexed in LB) ----
#pragma unroll
    for (int r = 0; r < 32; ++r)
        a[r] = f2fma(a[r], ldsv(phiRc + r), f2mul(swp(a[r]), ldsv(phiRs + r)));

    // ======================= Epilogue on psi (LB: j=(t<<5)|r) ================
    // (identical to the validated R9/R11/R12/R14 epilogue)

    // Z-part: tot + 5 signed r-sums via quad butterflies.
    u64 tot = 0, S10 = 0, S18 = 0, S1C = 0, S1E = 0, S1F = 0;
#pragma unroll
    for (int r = 0; r < 32; r += 4) {
        u64 q0 = f2mul(a[r],     a[r]);
        u64 q1 = f2mul(a[r + 1], a[r + 1]);
        u64 q2 = f2mul(a[r + 2], a[r + 2]);
        u64 q3 = f2mul(a[r + 3], a[r + 3]);
        u64 s01 = f2add(q0, q1), s23 = f2add(q2, q3);
        u64 d01 = f2sub(q0, q1), d23 = f2sub(q2, q3);
        u64 ss = f2add(s01, s23);
        u64 sd = f2sub(s01, s23);
        u64 df = f2sub(d01, d23);
        const int pq = ((r >> 4) ^ (r >> 3) ^ (r >> 2)) & 1;
        tot = f2add(tot, ss);
        S10 = (r & 0x10)                  ? f2sub(S10, ss) : f2add(S10, ss);
        S18 = (((r >> 4) ^ (r >> 3)) & 1) ? f2sub(S18, ss) : f2add(S18, ss);
        S1C = pq ? f2sub(S1C, ss) : f2add(S1C, ss);
        S1E = pq ? f2sub(S1E, sd) : f2add(S1E, sd);
        S1F = pq ? f2sub(S1F, df) : f2add(S1F, df);
    }
    const float tot_s = hadd(tot);
    const float s10 = hadd(S10), s18 = hadd(S18), s1C = hadd(S1C);
    const float s1E = hadd(S1E), s1F = hadd(S1F);

    // X in-register wires 5..8 (partners r^0x18, r^0xC, r^6, r^3), half-sums.
    u64 X5 = 0, X6 = 0, X7 = 0, X8 = 0;
#pragma unroll
    for (int r = 0; r < 32; ++r) {
        if (!(r & 0x10)) X5 = f2fma(a[r], a[r ^ 0x18], X5);
        if (!(r & 0x08)) X6 = f2fma(a[r], a[r ^ 0x0C], X6);
        if (!(r & 0x04)) X7 = f2fma(a[r], a[r ^ 0x06], X7);
        if (!(r & 0x02)) X8 = f2fma(a[r], a[r ^ 0x03], X8);
    }
    const float x5 = hadd(X5), x6 = hadd(X6), x7 = hadd(X7), x8 = hadd(X8);

    // Straddler X wires, half-sums:
    //  w4 (m=0x30): pairs (t, r<16) <-> (t^1, r+16)
    //  w9 (m=0x301): pairs (t, r even) <-> (t^0x18, r+1)
    u64 X4 = 0, X9 = 0;
#pragma unroll
    for (int r = 0; r < 16; ++r) {
        u64 p4 = __shfl_xor_sync(0xffffffffu, a[r + 16], 1);
        X4 = f2fma(a[r], p4, X4);
    }
#pragma unroll
    for (int r = 0; r < 32; r += 2) {
        u64 p9 = __shfl_xor_sync(0xffffffffu, a[r + 1], 0x18);
        X9 = f2fma(a[r], p9, X9);
    }
    const float x4 = hadd(X4), x9 = hadd(X9);

    // ---- Transpose LB -> LA for wires 0..3 X-terms ----
    __syncwarp();
#pragma unroll
    for (int r = 0; r < 32; ++r) sb[swz((t << 5) | r)] = a[r];
    __syncwarp();
#pragma unroll
    for (int r = 0; r < 32; ++r) a[r] = sb[swz((r << 5) | t)];

    // X in-register wires 0..3 in LA (partners r^0x18, r^0xC, r^6, r^3), half-sums.
    u64 X0 = 0, X1 = 0, X2 = 0, X3 = 0;
#pragma unroll
    for (int r = 0; r < 32; ++r) {
        if (!(r & 0x10)) X0 = f2fma(a[r], a[r ^ 0x18], X0);
        if (!(r & 0x08)) X1 = f2fma(a[r], a[r ^ 0x0C], X1);
        if (!(r & 0x04)) X2 = f2fma(a[r], a[r ^ 0x06], X2);
        if (!(r & 0x02)) X3 = f2fma(a[r], a[r ^ 0x03], X3);
    }
    const float x0 = hadd(X0), x1 = hadd(X1), x2 = hadd(X2), x3 = hadd(X3);

    // Thread-parity signs for the Z parts (t-masks from M_b >> 5).
    const float sgA = (__popc(t & 0x0F) & 1) ? -1.f : 1.f;   // wire 0
    const float sgB = (__popc(t & 0x18) & 1) ? -1.f : 1.f;   // wire 1
    const float sgC = (__popc(t & 0x1C) & 1) ? -1.f : 1.f;   // wire 2
    const float sgD = (__popc(t & 0x1E) & 1) ? -1.f : 1.f;   // wire 3
    const float sgE = (__popc(t & 0x1F) & 1) ? -1.f : 1.f;   // wires 4..9

    // Combine: E_q = cz[q] * Z_q + cxw[q] * X_q  (per-thread partials).
    float e[NW];
    e[0] = cz[0] * (sgA * s1F)   + cxw[0] * x0;
    e[1] = cz[1] * (sgB * tot_s) + cxw[1] * x1;
    e[2] = cz[2] * (sgC * tot_s) + cxw[2] * x2;
    e[3] = cz[3] * (sgD * tot_s) + cxw[3] * x3;
    e[4] = cz[4] * (sgE * tot_s) + cxw[4] * x4;
    e[5] = cz[5] * (sgE * s10)   + cxw[5] * x5;
    e[6] = cz[6] * (sgE * s18)   + cxw[6] * x6;
    e[7] = cz[7] * (sgE * s1C)   + cxw[7] * x7;
    e[8] = cz[8] * (sgE * s1E)   + cxw[8] * x8;
    e[9] = cz[9] * (sgE * s1F)   + cxw[9] * x9;

    // Packed warp reduction of 10 values as 5 u64.
    u64 vp[5];
#pragma unroll
    for (int j = 0; j < 5; ++j) vp[j] = pk(e[2 * j], e[2 * j + 1]);
#pragma unroll
    for (int off = 16; off; off >>= 1) {
#pragma unroll
        for (int j = 0; j < 5; ++j)
            vp[j] = f2add(vp[j], __shfl_xor_sync(0xffffffffu, vp[j], off));
    }
    if (t == 0) {
#pragma unroll
        for (int j = 0; j < 5; ++j) {
            float vx, vy;
            upk(vp[j], vx, vy);
            out[(size_t)n * NW + 2 * j]     = vx;
            out[(size_t)n * NW + 2 * j + 1] = vy;
        }
    }
}

extern "C" void kernel_launch(void* const* d_in, const int* in_sizes, int n_in,
                              void* d_out, int out_size) {
    const float* x   = (const float*)d_in[0];
    const float* rx0 = (const float*)d_in[1];
    const float* ry0 = (const float*)d_in[2];
    const float* ry1 = (const float*)d_in[3];
    float* out = (float*)d_out;
    const int n_states = in_sizes[0] / DIM;            // 4096
    qsa15_kernel<<<n_states / WARPS_PER_BLK, 32 * WARPS_PER_BLK>>>(x, rx0, ry0, ry1, out);
}